// round 2
// baseline (speedup 1.0000x reference)
#include <cuda_runtime.h>
#include <cstdint>

// ---------------------------------------------------------------------------
// Fixed problem shapes
// ---------------------------------------------------------------------------
static constexpr int       NNODE = 32768;
static constexpr long long ND    = 32768LL * 128;   // 4,194,304
static constexpr int       EUP   = 524288;
static constexpr int       EDN   = 524288;
static constexpr int       EB    = 131072;

// ---------------------------------------------------------------------------
// Scratch (__device__ globals; allocation-free rule)
// ---------------------------------------------------------------------------
__device__ float  g_xWu[4194304];
__device__ float  g_xWd[4194304];
__device__ float  g_acc[12582912];   // 3 branches: out_msg + x
__device__ float  g_z1 [12582912];
__device__ float  g_z2 [12582912];
__device__ float  g_zc [4194304];
__device__ float  g_sums[1792];      // 7 BN stages * (128 sum + 128 sumsq)
__device__ float2 g_aff [896];       // 7 stages * 128 (scale, shift)

// ---------------------------------------------------------------------------
// Helpers
// ---------------------------------------------------------------------------
__device__ __forceinline__ unsigned tf32u(float x) {
    unsigned r;
    asm("cvt.rna.tf32.f32 %0, %1;" : "=r"(r) : "f"(x));
    return r;
}
__device__ __forceinline__ float uaf(unsigned u) { return __uint_as_float(u); }
__device__ __forceinline__ unsigned fau(float f) { return __float_as_uint(f); }

__device__ __forceinline__ void mma8(float* d, unsigned a0, unsigned a1,
                                     unsigned a2, unsigned a3,
                                     unsigned b0, unsigned b1) {
    asm volatile(
        "mma.sync.aligned.m16n8k8.row.col.f32.tf32.tf32.f32 "
        "{%0,%1,%2,%3},{%4,%5,%6,%7},{%8,%9},{%0,%1,%2,%3};\n"
        : "+f"(d[0]), "+f"(d[1]), "+f"(d[2]), "+f"(d[3])
        : "r"(a0), "r"(a1), "r"(a2), "r"(a3), "r"(b0), "r"(b1));
}

__device__ __forceinline__ void red4(float* p, float4 v) {
    asm volatile("red.global.add.v4.f32 [%0], {%1,%2,%3,%4};"
                 :: "l"(p), "f"(v.x), "f"(v.y), "f"(v.z), "f"(v.w) : "memory");
}

// Fragment-store mapping for W columns.
// Within each 64-col warp half, logical col L is produced by thread group
// c=(L>>4)&3 at n-tile t=(L>>1)&7, j=L&1, so every thread's 16 outputs are
// the contiguous logical columns [16c, 16c+16).
__device__ __forceinline__ int wfrag_slot(int k, int n) {
    int half = n >> 6, nl = n & 63;
    int t  = (nl >> 1) & 7;
    int m  = (((nl >> 4) & 3) << 1) | (nl & 1);   // B col within n8 tile
    int ln = (m << 2) | (k & 3);
    return (((((k >> 3) << 1) | half) << 3 | t) << 5) | ln;
}

// ---------------------------------------------------------------------------
// init: acc[k]=x for 3 branches; zero BN sums
// ---------------------------------------------------------------------------
__global__ void __launch_bounds__(256) k_init(const float* __restrict__ x) {
    long long i = (long long)blockIdx.x * 256 + threadIdx.x;   // float4 index
    float4 v = ((const float4*)x)[i];
    ((float4*)g_acc)[i]           = v;
    ((float4*)g_acc)[i + 1048576] = v;
    ((float4*)g_acc)[i + 2097152] = v;
    if (blockIdx.x == 0)
        for (int j = threadIdx.x; j < 1792; j += 256) g_sums[j] = 0.f;
}

// ---------------------------------------------------------------------------
// Edge GEMM + gather-add-relu-scatter.
// Q = attr @ Wb (tf32), m = relu(Q + P[src]), red-add to out[dst].
// Tile: 64 edges x 128 cols, K=128 resident. 4 tiles per block.
// smem: W fragments (65536 B) + A tile 64x132 f32 (33792 B) = 99328 B
// ---------------------------------------------------------------------------
__global__ void __launch_bounds__(256, 2)
k_edge(const float* __restrict__ attr, const float* __restrict__ Wb,
       const float* __restrict__ P, const int* __restrict__ idx,
       float* __restrict__ outp, int E) {
    extern __shared__ char smemraw[];
    float* Wsf = (float*)smemraw;               // 16384 floats (b0,b1 pairs)
    float* As  = (float*)(smemraw + 65536);     // 64 x 132

    int tid = threadIdx.x;

    // W fragment fill (once per block), tf32-rounded
    for (int i = tid; i < 4096; i += 256) {
        int k = i >> 5, n4 = (i & 31) << 2;
        float4 w = *(const float4*)(Wb + k * 128 + n4);
        float wv[4] = {w.x, w.y, w.z, w.w};
#pragma unroll
        for (int j = 0; j < 4; j++) {
            int slot = wfrag_slot(k, n4 + j);
            int jb = (k >> 2) & 1;
            Wsf[slot * 2 + jb] = uaf(tf32u(wv[j]));
        }
    }

    int lane = tid & 31, wrp = tid >> 5;
    int wr = wrp >> 1, wc = wrp & 1;
    int arow = (wr << 4) + (lane >> 2);
    int acol = lane & 3;

    for (int tt = 0; tt < 4; tt++) {
        int ebase = ((blockIdx.x << 2) + tt) << 6;
        __syncthreads();
        // A tile (dense attr rows), tf32-rounded
        for (int i = tid; i < 2048; i += 256) {
            int r = i >> 5, c4 = (i & 31) << 2;
            float4 a = *(const float4*)(attr + (long long)(ebase + r) * 128 + c4);
            float4 s = make_float4(uaf(tf32u(a.x)), uaf(tf32u(a.y)),
                                   uaf(tf32u(a.z)), uaf(tf32u(a.w)));
            *(float4*)(As + r * 132 + c4) = s;
        }
        __syncthreads();

        float acc[8][4];
#pragma unroll
        for (int t = 0; t < 8; t++)
#pragma unroll
            for (int j = 0; j < 4; j++) acc[t][j] = 0.f;

#pragma unroll
        for (int ks = 0; ks < 16; ks++) {
            int k0 = ks << 3;
            unsigned a0 = fau(As[arow * 132 + k0 + acol]);
            unsigned a1 = fau(As[(arow + 8) * 132 + k0 + acol]);
            unsigned a2 = fau(As[arow * 132 + k0 + acol + 4]);
            unsigned a3 = fau(As[(arow + 8) * 132 + k0 + acol + 4]);
            const float2* bbase =
                (const float2*)Wsf + ((((ks << 1) | wc) << 3) << 5) + lane;
#pragma unroll
            for (int t = 0; t < 8; t++) {
                float2 b = bbase[t << 5];
                mma8(acc[t], a0, a1, a2, a3, fau(b.x), fau(b.y));
            }
        }

        // epilogue: + P[src], relu, red-add to out[dst]
        int cg = lane & 3;
        int colbase = (wc << 6) + (cg << 4);
#pragma unroll
        for (int rr = 0; rr < 2; rr++) {
            int e = ebase + (wr << 4) + (lane >> 2) + (rr << 3);
            int dst = idx[e];
            int src = idx[E + e];
            const float4* pp = (const float4*)(P + (long long)src * 128 + colbase);
            float* op = outp + (long long)dst * 128 + colbase;
#pragma unroll
            for (int q = 0; q < 4; q++) {
                float4 pv = pp[q];
                float4 v;
                v.x = fmaxf(acc[2 * q][rr * 2 + 0] + pv.x, 0.f);
                v.y = fmaxf(acc[2 * q][rr * 2 + 1] + pv.y, 0.f);
                v.z = fmaxf(acc[2 * q + 1][rr * 2 + 0] + pv.z, 0.f);
                v.w = fmaxf(acc[2 * q + 1][rr * 2 + 1] + pv.w, 0.f);
                red4(op + (q << 2), v);
            }
        }
    }
}

// ---------------------------------------------------------------------------
// Node GEMM (tf32x2 split, ~fp32 accuracy): C = op(A) @ W + bias
//   op(A) = relu(A*scale+shift) per column if affine != null, else A.
//   K in {128, 384}; K>128 reads A segments at A + (k>>7)*segStride.
// Tile 64 x 128, K-chunks of 64.
// smem: W frags hi/lo float4 (65536 B) + A hi/lo 64x68 float2 (34816) = 100352
// ---------------------------------------------------------------------------
__global__ void __launch_bounds__(256, 2)
k_node(const float* __restrict__ A, long long aZ, long long segStride,
       const float* __restrict__ W, long long wZ,
       const float* __restrict__ bias, int bZ,
       const float2* __restrict__ affine, int affZ,
       float* __restrict__ C, long long cZ, int K) {
    extern __shared__ char smemraw[];
    float*  Wsf = (float*)smemraw;                 // 4096 float4 as floats
    float2* As2 = (float2*)(smemraw + 65536);      // 64 x 68 (hi, lo)

    int z = blockIdx.z;
    int tid = threadIdx.x;
    int lane = tid & 31, wrp = tid >> 5;
    int wr = wrp >> 1, wc = wrp & 1;
    int row0 = blockIdx.x << 6;

    const float*  Az   = A + (long long)z * aZ;
    const float*  Wz   = W + (long long)z * wZ;
    const float2* affz = affine ? (affine + (long long)z * affZ) : (const float2*)0;

    int arow = (wr << 4) + (lane >> 2);
    int acol = lane & 3;

    float acc[8][4];
#pragma unroll
    for (int t = 0; t < 8; t++)
#pragma unroll
        for (int j = 0; j < 4; j++) acc[t][j] = 0.f;

    for (int kc = 0; kc < K; kc += 64) {
        __syncthreads();
        // W chunk (64 rows), split hi/lo, fragment layout
        for (int i = tid; i < 2048; i += 256) {
            int k = i >> 5, n4 = (i & 31) << 2;
            float4 w = *(const float4*)(Wz + (long long)(kc + k) * 128 + n4);
            float wv[4] = {w.x, w.y, w.z, w.w};
#pragma unroll
            for (int j = 0; j < 4; j++) {
                int slot = wfrag_slot(k, n4 + j);
                int jb = (k >> 2) & 1;
                float hi = uaf(tf32u(wv[j]));
                float lo = uaf(tf32u(wv[j] - hi));
                Wsf[slot * 4 + jb]     = hi;
                Wsf[slot * 4 + 2 + jb] = lo;
            }
        }
        // A chunk (64 rows x 64 k), optional bn-relu affine, split hi/lo
        {
            int seg = kc >> 7, kin = kc & 127;
            for (int i = tid; i < 1024; i += 256) {
                int r = i >> 4, c4 = (i & 15) << 2;
                float4 a = *(const float4*)(Az + (long long)seg * segStride +
                                            (long long)(row0 + r) * 128 + kin + c4);
                float av[4] = {a.x, a.y, a.z, a.w};
#pragma unroll
                for (int j = 0; j < 4; j++) {
                    float v = av[j];
                    if (affz) {
                        float2 sc = affz[kc + c4 + j];
                        v = fmaxf(fmaf(v, sc.x, sc.y), 0.f);
                    }
                    float hi = uaf(tf32u(v));
                    float lo = uaf(tf32u(v - hi));
                    As2[r * 68 + c4 + j] = make_float2(hi, lo);
                }
            }
        }
        __syncthreads();

#pragma unroll
        for (int ks = 0; ks < 8; ks++) {
            int k0 = ks << 3;
            float2 a0 = As2[arow * 68 + k0 + acol];
            float2 a1 = As2[(arow + 8) * 68 + k0 + acol];
            float2 a2 = As2[arow * 68 + k0 + acol + 4];
            float2 a3 = As2[(arow + 8) * 68 + k0 + acol + 4];
            unsigned h0 = fau(a0.x), h1 = fau(a1.x), h2 = fau(a2.x), h3 = fau(a3.x);
            unsigned l0 = fau(a0.y), l1 = fau(a1.y), l2 = fau(a2.y), l3 = fau(a3.y);
            const float4* bbase =
                (const float4*)Wsf + ((((ks << 1) | wc) << 3) << 5) + lane;
#pragma unroll
            for (int t = 0; t < 8; t++) {
                float4 b = bbase[t << 5];
                unsigned bh0 = fau(b.x), bh1 = fau(b.y);
                unsigned bl0 = fau(b.z), bl1 = fau(b.w);
                mma8(acc[t], h0, h1, h2, h3, bh0, bh1);
                mma8(acc[t], h0, h1, h2, h3, bl0, bl1);
                mma8(acc[t], l0, l1, l2, l3, bh0, bh1);
            }
        }
    }

    // epilogue: C = acc + bias (raw pre-BN), vectorized stores
    int cg = lane & 3;
    int colbase = (wc << 6) + (cg << 4);
    const float* bp = bias + (long long)z * bZ + colbase;
    float4 bb[4] = {*(const float4*)(bp),     *(const float4*)(bp + 4),
                    *(const float4*)(bp + 8), *(const float4*)(bp + 12)};
    float* Cz = C + (long long)z * cZ;
#pragma unroll
    for (int rr = 0; rr < 2; rr++) {
        int rg = row0 + (wr << 4) + (lane >> 2) + (rr << 3);
        float* cp = Cz + (long long)rg * 128 + colbase;
#pragma unroll
        for (int q = 0; q < 4; q++) {
            float4 v;
            v.x = acc[2 * q][rr * 2 + 0] + bb[q].x;
            v.y = acc[2 * q][rr * 2 + 1] + bb[q].y;
            v.z = acc[2 * q + 1][rr * 2 + 0] + bb[q].z;
            v.w = acc[2 * q + 1][rr * 2 + 1] + bb[q].w;
            *(float4*)(cp + (q << 2)) = v;
        }
    }
}

// ---------------------------------------------------------------------------
// Boundary: out[dst] += boundary_attr[gidx]   (identity message nn)
// ---------------------------------------------------------------------------
__global__ void __launch_bounds__(256)
k_boundary(const float* __restrict__ battr, const int* __restrict__ idx,
           float* __restrict__ outp, int E) {
    int t = blockIdx.x * 256 + threadIdx.x;
    int e = t >> 5, q = t & 31;
    int gi  = idx[e];
    int dst = idx[E + e];
    float4 v = *(const float4*)(battr + (long long)gi * 128 + (q << 2));
    red4(outp + (long long)dst * 128 + (q << 2), v);
}

// ---------------------------------------------------------------------------
// BN column stats: sum & sumsq over the 32768 rows (per branch z)
// ---------------------------------------------------------------------------
__global__ void __launch_bounds__(128)
k_stats(const float* __restrict__ A, long long zStride, float* __restrict__ sums) {
    const float* p = A + (long long)blockIdx.z * zStride +
                     (long long)blockIdx.x * 256 * 128 + threadIdx.x;
    float s = 0.f, q = 0.f;
#pragma unroll 8
    for (int r = 0; r < 256; r++) {
        float v = p[(long long)r * 128];
        s += v;
        q += v * v;
    }
    atomicAdd(&sums[blockIdx.z * 256 + threadIdx.x], s);
    atomicAdd(&sums[blockIdx.z * 256 + 128 + threadIdx.x], q);
}

__global__ void k_fin(const float* __restrict__ sums, const float* __restrict__ g,
                      const float* __restrict__ be, float2* __restrict__ aff, int n) {
    int i = blockIdx.x * 128 + threadIdx.x;
    if (i < n) {
        int zz = i >> 7, col = i & 127;
        float s = sums[zz * 256 + col], qq = sums[zz * 256 + 128 + col];
        float mean = s * (1.f / 32768.f);
        float var  = qq * (1.f / 32768.f) - mean * mean;
        float sc   = g[i] * rsqrtf(var + 1e-5f);
        aff[i] = make_float2(sc, fmaf(-mean, sc, be[i]));
    }
}

// ---------------------------------------------------------------------------
// Final: out = relu(bn(zc))
// ---------------------------------------------------------------------------
__global__ void __launch_bounds__(256) k_out(float* __restrict__ outp) {
    long long i = (long long)blockIdx.x * 256 + threadIdx.x;   // float4 index
    float4 v = ((const float4*)g_zc)[i];
    int col = (int)((i & 31) << 2);
    const float2* a = g_aff + 768 + col;
    float4 o;
    o.x = fmaxf(fmaf(v.x, a[0].x, a[0].y), 0.f);
    o.y = fmaxf(fmaf(v.y, a[1].x, a[1].y), 0.f);
    o.z = fmaxf(fmaf(v.z, a[2].x, a[2].y), 0.f);
    o.w = fmaxf(fmaf(v.w, a[3].x, a[3].y), 0.f);
    ((float4*)outp)[i] = o;
}

// ---------------------------------------------------------------------------
// kernel_launch
// ---------------------------------------------------------------------------
extern "C" void kernel_launch(void* const* d_in, const int* in_sizes, int n_in,
                              void* d_out, int out_size) {
    (void)in_sizes; (void)n_in; (void)out_size;

    const float* x       = (const float*)d_in[0];
    const int*   up_idx  = (const int*)d_in[1];
    const int*   dn_idx  = (const int*)d_in[2];
    const int*   b_idx   = (const int*)d_in[3];
    const float* up_attr = (const float*)d_in[4];
    const float* dn_attr = (const float*)d_in[5];
    const float* b_attr  = (const float*)d_in[6];
    const float* w_up    = (const float*)d_in[7];
    const float* b_up    = (const float*)d_in[8];
    const float* w_dn    = (const float*)d_in[9];
    const float* b_dn    = (const float*)d_in[10];
    const float* w1      = (const float*)d_in[11];
    const float* bb1     = (const float*)d_in[12];
    const float* g1      = (const float*)d_in[13];
    const float* be1     = (const float*)d_in[14];
    const float* w2      = (const float*)d_in[15];
    const float* bb2     = (const float*)d_in[16];
    const float* g2      = (const float*)d_in[17];
    const float* be2     = (const float*)d_in[18];
    const float* wcomb   = (const float*)d_in[19];
    const float* bcomb   = (const float*)d_in[20];
    const float* gcomb   = (const float*)d_in[21];
    const float* becomb  = (const float*)d_in[22];
    float* out = (float*)d_out;

    void *p_xWu, *p_xWd, *p_acc, *p_z1, *p_z2, *p_zc, *p_sums, *p_aff;
    cudaGetSymbolAddress(&p_xWu, g_xWu);
    cudaGetSymbolAddress(&p_xWd, g_xWd);
    cudaGetSymbolAddress(&p_acc, g_acc);
    cudaGetSymbolAddress(&p_z1, g_z1);
    cudaGetSymbolAddress(&p_z2, g_z2);
    cudaGetSymbolAddress(&p_zc, g_zc);
    cudaGetSymbolAddress(&p_sums, g_sums);
    cudaGetSymbolAddress(&p_aff, g_aff);
    float*  xWu  = (float*)p_xWu;
    float*  xWd  = (float*)p_xWd;
    float*  acc  = (float*)p_acc;
    float*  z1   = (float*)p_z1;
    float*  z2   = (float*)p_z2;
    float*  zc   = (float*)p_zc;
    float*  sums = (float*)p_sums;
    float2* aff  = (float2*)p_aff;

    const int ESM = 99328, NSM = 100352;
    cudaFuncSetAttribute(k_edge, cudaFuncAttributeMaxDynamicSharedMemorySize, ESM);
    cudaFuncSetAttribute(k_node, cudaFuncAttributeMaxDynamicSharedMemorySize, NSM);

    // 1) acc[k] = x, zero stats
    k_init<<<4096, 256>>>(x);

    // 2) P = x @ W_top + b  (rows 0..127 of msg_*_w)
    k_node<<<dim3(512, 1, 1), 256, NSM>>>(x, 0, 0, w_up, 0, b_up, 0,
                                          (const float2*)0, 0, xWu, 0, 128);
    k_node<<<dim3(512, 1, 1), 256, NSM>>>(x, 0, 0, w_dn, 0, b_dn, 0,
                                          (const float2*)0, 0, xWd, 0, 128);

    // 3) edge message GEMMs + scatter (W_bot = rows 128..255)
    k_edge<<<2048, 256, ESM>>>(up_attr, w_up + 16384, xWu, up_idx, acc, EUP);
    k_edge<<<2048, 256, ESM>>>(dn_attr, w_dn + 16384, xWd, dn_idx, acc + ND, EDN);

    // 4) boundary scatter
    k_boundary<<<16384, 256>>>(b_attr, b_idx, acc + 2 * ND, EB);

    // 5) z1[k] = h[k] @ w1[k] + b1[k]
    k_node<<<dim3(512, 1, 3), 256, NSM>>>(acc, ND, 0, w1, 16384, bb1, 128,
                                          (const float2*)0, 0, z1, ND, 128);
    k_stats<<<dim3(128, 1, 3), 128>>>(z1, ND, sums);
    k_fin<<<3, 128>>>(sums, g1, be1, aff, 384);

    // 6) z2[k] = relu(bn(z1[k])) @ w2[k] + b2[k]
    k_node<<<dim3(512, 1, 3), 256, NSM>>>(z1, ND, 0, w2, 16384, bb2, 128,
                                          aff, 128, z2, ND, 128);
    k_stats<<<dim3(128, 1, 3), 128>>>(z2, ND, sums + 768);
    k_fin<<<3, 128>>>(sums + 768, g2, be2, aff + 384, 384);

    // 7) zc = cat(relu(bn(z2))) @ comb_w + comb_b   (K = 384, 3 segments)
    k_node<<<dim3(512, 1, 1), 256, NSM>>>(z2, 0, ND, wcomb, 0, bcomb, 0,
                                          aff + 384, 0, zc, 0, 384);
    k_stats<<<dim3(128, 1, 1), 128>>>(zc, 0, sums + 1536);
    k_fin<<<1, 128>>>(sums + 1536, gcomb, becomb, aff + 768, 128);

    // 8) out = relu(bn(zc))
    k_out<<<4096, 256>>>(out);
}